// round 16
// baseline (speedup 1.0000x reference)
#include <cuda_runtime.h>
#include <cuda_bf16.h>
#include <cstdint>

#define NN 100000
#define NR 100096   // rows padded to 128-multiple: guard-free tile staging
#define NT 782      // NR / 128
#define NE 600000
#define HID 128
#define OUTD 64
#define PGRID 148   // persistent grid

// ---------------- scratch (device globals; no allocations allowed) ----------
__device__ __nv_bfloat16 g_hb[4 * 2 * NR * HID];  // h states: hi/lo planes
__device__ __nv_bfloat16 g_tb[2 * NR * HID];      // t images (also x images)
__device__ __nv_bfloat16 g_Wb[4 * 2 * HID * HID]; // per layer: hi[128][128], lo
__device__ __nv_bfloat16 g_WoB[2 * OUTD * 512];   // W_out: hi[64][512], lo
__device__ float g_oacc[NR * OUTD];               // partial final accumulator
__device__ int   g_off[NN + 1];
__device__ int   g_deg[NN];
__device__ int   g_cur[NN];
__device__ int   g_srcs[NE];
__device__ int   g_src[NE];
__device__ int   g_dst[NE];
__device__ int   g_is64;
__device__ int   g_bsum[128];

// ---------------- helpers -----------------------------------------------------
__device__ __forceinline__ uint32_t smem_u32(const void* p) {
    uint32_t a;
    asm("{ .reg .u64 t; cvta.to.shared.u64 t, %1; cvt.u32.u64 %0, t; }" : "=r"(a) : "l"(p));
    return a;
}
__device__ __forceinline__ float lo16f(uint32_t u) { return __uint_as_float(u << 16); }
__device__ __forceinline__ float hi16f(uint32_t u) { return __uint_as_float(u & 0xffff0000u); }

__device__ __forceinline__ void split2(float a, float b, uint32_t& hw, uint32_t& lw) {
    __nv_bfloat16 ha = __float2bfloat16_rn(a), hb = __float2bfloat16_rn(b);
    __nv_bfloat16 la = __float2bfloat16_rn(a - __bfloat162float(ha));
    __nv_bfloat16 lb = __float2bfloat16_rn(b - __bfloat162float(hb));
    hw = (uint32_t)__bfloat16_as_ushort(ha) | ((uint32_t)__bfloat16_as_ushort(hb) << 16);
    lw = (uint32_t)__bfloat16_as_ushort(la) | ((uint32_t)__bfloat16_as_ushort(lb) << 16);
}
__device__ __forceinline__ void split4(float4 v, uint2& hi, uint2& lo) {
    split2(v.x, v.y, hi.x, lo.x);
    split2(v.z, v.w, hi.y, lo.y);
}

__device__ __forceinline__ void mma_bf16(float* c, uint32_t a0, uint32_t a1,
                                         uint32_t a2, uint32_t a3,
                                         uint32_t b0, uint32_t b1) {
    asm volatile(
        "mma.sync.aligned.m16n8k16.row.col.f32.bf16.bf16.f32 "
        "{%0,%1,%2,%3},{%4,%5,%6,%7},{%8,%9},{%0,%1,%2,%3};"
        : "+f"(c[0]), "+f"(c[1]), "+f"(c[2]), "+f"(c[3])
        : "r"(a0), "r"(a1), "r"(a2), "r"(a3), "r"(b0), "r"(b1));
}

#define LDM4(r0, r1, r2, r3, addr) \
    asm volatile("ldmatrix.sync.aligned.m8n8.x4.shared.b16 {%0,%1,%2,%3}, [%4];" \
                 : "=r"(r0), "=r"(r1), "=r"(r2), "=r"(r3) : "r"(addr))

#define CPA16(dst, src) \
    asm volatile("cp.async.cg.shared.global [%0], [%1], 16;" :: "r"(dst), "l"(src) : "memory")
#define CPA_COMMIT() asm volatile("cp.async.commit_group;" ::: "memory")
#define CPA_WAIT0()  asm volatile("cp.async.wait_group 0;" ::: "memory")
#define CPA_WAIT1()  asm volatile("cp.async.wait_group 1;" ::: "memory")

// ---------------- edge dtype detection + decode + degree count ---------------
__global__ void k_detect(const unsigned* __restrict__ raw) {
    if (threadIdx.x == 0) {
        int is64 = 1;
        for (int i = 1; i < 128; i += 2)
            if (raw[i] != 0u) { is64 = 0; break; }
        g_is64 = is64;
    }
}

__global__ void k_zero() {
    int i = blockIdx.x * blockDim.x + threadIdx.x;
    if (i < NN) { g_deg[i] = 0; g_cur[i] = 0; }
}

__global__ void k_decode(const void* __restrict__ raw) {
    int e = blockIdx.x * blockDim.x + threadIdx.x;
    if (e >= NE) return;
    int s, d;
    if (g_is64) {
        const long long* p = (const long long*)raw;
        s = (int)p[e]; d = (int)p[NE + e];
    } else {
        const int* p = (const int*)raw;
        s = p[e]; d = p[NE + e];
    }
    g_src[e] = s;
    g_dst[e] = d;
    atomicAdd(&g_deg[d], 1);
}

// ---------------- CSR build ---------------------------------------------------
__global__ void k_scan1() {
    __shared__ int sh[1024];
    int i = blockIdx.x * 1024 + threadIdx.x;
    int v = (i < NN) ? g_deg[i] : 0;
    sh[threadIdx.x] = v;
    __syncthreads();
    for (int s = 1; s < 1024; s <<= 1) {
        int a = (threadIdx.x >= (unsigned)s) ? sh[threadIdx.x - s] : 0;
        __syncthreads();
        sh[threadIdx.x] += a;
        __syncthreads();
    }
    if (i < NN) g_deg[i] = sh[threadIdx.x];
    if (threadIdx.x == 1023) g_bsum[blockIdx.x] = sh[1023];
}
__global__ void k_scan2(int nb) {
    __shared__ int sh[128];
    int t = threadIdx.x;
    sh[t] = (t < nb) ? g_bsum[t] : 0;
    __syncthreads();
    if (t == 0) {
        int acc = 0;
        for (int i = 0; i < nb; i++) { int v = sh[i]; sh[i] = acc; acc += v; }
    }
    __syncthreads();
    if (t < nb) g_bsum[t] = sh[t];
}
__global__ void k_scan3() {
    int i = blockIdx.x * 1024 + threadIdx.x;
    if (i < NN) g_off[i + 1] = g_deg[i] + g_bsum[blockIdx.x];
    if (i == 0) g_off[0] = 0;
}
__global__ void k_fill() {
    int e = blockIdx.x * blockDim.x + threadIdx.x;
    if (e >= NE) return;
    int d = g_dst[e];
    int p = atomicAdd(&g_cur[d], 1);
    g_srcs[g_off[d] + p] = g_src[e];
}

// ---------------- weight / input preconversion (bf16 hi/lo images) ----------
__global__ void k_prepW(const float* __restrict__ W_in, const float* __restrict__ W_convs) {
    int idx = blockIdx.x * blockDim.x + threadIdx.x;   // 4*128*32
    if (idx >= 4 * 128 * 32) return;
    int l = idx >> 12;
    int rem = idx & 4095;
    int j = rem >> 5;
    int k4 = rem & 31;
    const float* W = (l == 0) ? W_in : (W_convs + (size_t)(l - 1) * 128 * 128);
    float4 v = ((const float4*)W)[j * 32 + k4];
    uint2 hp, lp; split4(v, hp, lp);
    char* base = (char*)(g_Wb + (size_t)l * 2 * 16384);
    *(uint2*)(base + j * 256 + k4 * 8) = hp;
    *(uint2*)(base + 32768 + j * 256 + k4 * 8) = lp;
}

__global__ void k_prepWo(const float* __restrict__ W_out) {
    int idx = blockIdx.x * blockDim.x + threadIdx.x;   // 64*128
    if (idx >= 64 * 128) return;
    int j = idx >> 7;
    int k4 = idx & 127;
    float4 v = ((const float4*)W_out)[j * 128 + k4];
    uint2 hp, lp; split4(v, hp, lp);
    char* base = (char*)g_WoB;
    *(uint2*)(base + j * 1024 + k4 * 8) = hp;
    *(uint2*)(base + 65536 + j * 1024 + k4 * 8) = lp;
}

__global__ void k_prepX(const float* __restrict__ x) {
    int i = blockIdx.x * blockDim.x + threadIdx.x;
    if (i >= NN * 32) return;
    float4 v = ((const float4*)x)[i];
    uint2 hp, lp; split4(v, hp, lp);
    ((uint2*)g_tb)[i] = hp;
    ((uint2*)(g_tb + (size_t)NR * HID))[i] = lp;
}

// ---------------- aggregation on images: t = h + seg_sum(h) ------------------
__global__ void k_agg(const __nv_bfloat16* __restrict__ himg) {
    int gw   = (blockIdx.x * blockDim.x + threadIdx.x) >> 5;
    int lane = threadIdx.x & 31;
    if (gw >= NN) return;
    const uint2* Hv = (const uint2*)himg;
    const uint2* Lv = (const uint2*)(himg + (size_t)NR * HID);
    size_t idx = (size_t)gw * 32 + lane;
    uint2 h = Hv[idx], l = Lv[idx];
    float a0 = lo16f(h.x) + lo16f(l.x);
    float a1 = hi16f(h.x) + hi16f(l.x);
    float a2 = lo16f(h.y) + lo16f(l.y);
    float a3 = hi16f(h.y) + hi16f(l.y);
    int s0 = g_off[gw], s1 = g_off[gw + 1];
    for (int j = s0; j < s1; j++) {
        size_t si = (size_t)g_srcs[j] * 32 + lane;
        uint2 hh = Hv[si], ll = Lv[si];
        a0 += lo16f(hh.x) + lo16f(ll.x);
        a1 += hi16f(hh.x) + hi16f(ll.x);
        a2 += lo16f(hh.y) + lo16f(ll.y);
        a3 += hi16f(hh.y) + hi16f(ll.y);
    }
    uint2 hp, lp;
    split2(a0, a1, hp.x, lp.x);
    split2(a2, a3, hp.y, lp.y);
    ((uint2*)g_tb)[idx] = hp;
    ((uint2*)(g_tb + (size_t)NR * HID))[idx] = lp;
}

// ---------------- persistent HMMA GEMM: C = A @ W^T + b ----------------------
#define SP 272
#define WOFF 0
#define ABUF 69632
__global__ void __launch_bounds__(256, 1)
k_gemm_p(const __nv_bfloat16* __restrict__ Aimg, const __nv_bfloat16* __restrict__ Wimg,
         const float* __restrict__ bias, __nv_bfloat16* __restrict__ Cimg, int nrows) {
    extern __shared__ char sm[];
    int tid = threadIdx.x, wid = tid >> 5, lane = tid & 31;
    int quad = lane >> 2, qi = lane & 3;
    int wm = wid >> 2, wn = wid & 3;
    uint32_t sb = smem_u32(sm);

    for (int i = tid; i < 4096; i += 256) {
        int pl = i >> 11, j = i & 2047, r = j >> 4, seg = (j & 15) * 16;
        CPA16(sb + WOFF + pl * 34816 + r * SP + seg,
              (const char*)Wimg + pl * 32768 + r * 256 + seg);
    }
    auto stageA = [&](int t, int b) {
        uint32_t base = sb + ABUF + b * 69632;
        const char* A0 = (const char*)Aimg;
        for (int i = tid; i < 4096; i += 256) {
            int pl = i >> 11, j = i & 2047, r = j >> 4, seg = (j & 15) * 16;
            CPA16(base + pl * 34816 + r * SP + seg,
                  A0 + (size_t)pl * NR * 256 + (size_t)(t * 128 + r) * 256 + seg);
        }
    };

    int t0 = blockIdx.x;
    stageA(t0, 0);
    CPA_COMMIT();

    uint32_t brow = (uint32_t)(((((lane >> 4) << 3) + (lane & 7)) * SP) + ((lane >> 3) & 1) * 16);

    int b = 0;
    for (int t = t0; t < NT; t += PGRID, b ^= 1) {
        int tn = t + PGRID;
        if (tn < NT) { stageA(tn, b ^ 1); CPA_COMMIT(); CPA_WAIT1(); }
        else CPA_WAIT0();
        __syncthreads();

        float acc[4][4][4];
#pragma unroll
        for (int mi = 0; mi < 4; mi++)
#pragma unroll
            for (int nj = 0; nj < 4; nj++)
#pragma unroll
                for (int c = 0; c < 4; c++) acc[mi][nj][c] = 0.f;

        uint32_t abase = sb + ABUF + b * 69632;
        uint32_t aH = abase + (uint32_t)((wm * 64 + (lane & 15)) * SP + (lane >> 4) * 16);
        uint32_t aL = aH + 34816;
        uint32_t bH = sb + WOFF + brow + (uint32_t)(wn * 32 * SP);
        uint32_t bL = bH + 34816;

        for (int s = 0; s < 8; s++) {
            uint32_t ah[4][4], al[4][4], bh[8], bl[8];
#pragma unroll
            for (int mi = 0; mi < 4; mi++) {
                LDM4(ah[mi][0], ah[mi][1], ah[mi][2], ah[mi][3], aH + mi * (16 * SP) + s * 32);
                LDM4(al[mi][0], al[mi][1], al[mi][2], al[mi][3], aL + mi * (16 * SP) + s * 32);
            }
#pragma unroll
            for (int nj = 0; nj < 2; nj++) {
                LDM4(bh[4 * nj], bh[4 * nj + 1], bh[4 * nj + 2], bh[4 * nj + 3],
                     bH + nj * (16 * SP) + s * 32);
                LDM4(bl[4 * nj], bl[4 * nj + 1], bl[4 * nj + 2], bl[4 * nj + 3],
                     bL + nj * (16 * SP) + s * 32);
            }
#pragma unroll
            for (int mi = 0; mi < 4; mi++)
#pragma unroll
                for (int nj = 0; nj < 2; nj++) {
                    mma_bf16(acc[mi][2 * nj],     ah[mi][0], ah[mi][1], ah[mi][2], ah[mi][3],
                             bh[4 * nj], bh[4 * nj + 1]);
                    mma_bf16(acc[mi][2 * nj + 1], ah[mi][0], ah[mi][1], ah[mi][2], ah[mi][3],
                             bh[4 * nj + 2], bh[4 * nj + 3]);
                }
#pragma unroll
            for (int mi = 0; mi < 4; mi++)
#pragma unroll
                for (int nj = 0; nj < 2; nj++) {
                    mma_bf16(acc[mi][2 * nj],     al[mi][0], al[mi][1], al[mi][2], al[mi][3],
                             bh[4 * nj], bh[4 * nj + 1]);
                    mma_bf16(acc[mi][2 * nj + 1], al[mi][0], al[mi][1], al[mi][2], al[mi][3],
                             bh[4 * nj + 2], bh[4 * nj + 3]);
                }
#pragma unroll
            for (int mi = 0; mi < 4; mi++)
#pragma unroll
                for (int nj = 0; nj < 2; nj++) {
                    mma_bf16(acc[mi][2 * nj],     ah[mi][0], ah[mi][1], ah[mi][2], ah[mi][3],
                             bl[4 * nj], bl[4 * nj + 1]);
                    mma_bf16(acc[mi][2 * nj + 1], ah[mi][0], ah[mi][1], ah[mi][2], ah[mi][3],
                             bl[4 * nj + 2], bl[4 * nj + 3]);
                }
        }

        char* Ch = (char*)Cimg;
        char* Cl = Ch + (size_t)NR * 256;
        int row0 = t * 128;
#pragma unroll
        for (int mi = 0; mi < 4; mi++) {
            int rA = row0 + wm * 64 + mi * 16 + quad, rB = rA + 8;
#pragma unroll
            for (int nj = 0; nj < 4; nj++) {
                int c = wn * 32 + nj * 8 + qi * 2;
                float bx = bias[c], by = bias[c + 1];
                uint32_t hw, lw;
                if (rA < nrows) {
                    split2(acc[mi][nj][0] + bx, acc[mi][nj][1] + by, hw, lw);
                    *(uint32_t*)(Ch + (size_t)rA * 256 + c * 2) = hw;
                    *(uint32_t*)(Cl + (size_t)rA * 256 + c * 2) = lw;
                }
                if (rB < nrows) {
                    split2(acc[mi][nj][2] + bx, acc[mi][nj][3] + by, hw, lw);
                    *(uint32_t*)(Ch + (size_t)rB * 256 + c * 2) = hw;
                    *(uint32_t*)(Cl + (size_t)rB * 256 + c * 2) = lw;
                }
            }
        }
        __syncthreads();
    }
}

// ---------------- partial final GEMM body: acc[8][4] = h_l tile @ Wout_l^T ---
// smem: AH@0 (34816), AL@34816, WH@69632 (17408), WL@87040; total 104448
#define SQ 272
__device__ __forceinline__ void part_body(int l, int t, int tid, int wid, int lane,
                                          uint32_t sb, float acc[8][4]) {
    for (int i = tid; i < 4096; i += 256) {
        int pl = i >> 11, j = i & 2047, r = j >> 4, seg = (j & 15) * 16;
        CPA16(sb + pl * 34816 + r * SQ + seg,
              (const char*)g_hb + (size_t)(l * 2 + pl) * NR * 256
              + (size_t)(t * 128 + r) * 256 + seg);
    }
    for (int i = tid; i < 2048; i += 256) {
        int pl = i >> 10, j = i & 1023, r = j >> 4, seg = (j & 15) * 16;
        CPA16(sb + 69632 + pl * 17408 + r * SQ + seg,
              (const char*)g_WoB + pl * 65536 + (size_t)r * 1024 + l * 256 + seg);
    }
    CPA_COMMIT();
    CPA_WAIT0();
    __syncthreads();

    uint32_t aH = sb + (uint32_t)((wid * 16 + (lane & 15)) * SQ + (lane >> 4) * 16);
    uint32_t aL = aH + 34816;
    uint32_t brow = (uint32_t)(((((lane >> 4) << 3) + (lane & 7)) * SQ) + ((lane >> 3) & 1) * 16);
    uint32_t bHb = sb + 69632 + brow;
    uint32_t bLb = bHb + 17408;

#pragma unroll
    for (int q = 0; q < 8; q++)
#pragma unroll
        for (int c = 0; c < 4; c++) acc[q][c] = 0.f;

    for (int s = 0; s < 8; s++) {
        uint32_t ah0, ah1, ah2, ah3, al0, al1, al2, al3;
        uint32_t bh[4][4], bl[4][4];
        LDM4(ah0, ah1, ah2, ah3, aH + s * 32);
        LDM4(al0, al1, al2, al3, aL + s * 32);
#pragma unroll
        for (int t2 = 0; t2 < 4; t2++) {
            LDM4(bh[t2][0], bh[t2][1], bh[t2][2], bh[t2][3], bHb + t2 * (16 * SQ) + s * 32);
            LDM4(bl[t2][0], bl[t2][1], bl[t2][2], bl[t2][3], bLb + t2 * (16 * SQ) + s * 32);
        }
#pragma unroll
        for (int t2 = 0; t2 < 4; t2++) {
            mma_bf16(acc[2 * t2],     ah0, ah1, ah2, ah3, bh[t2][0], bh[t2][1]);
            mma_bf16(acc[2 * t2 + 1], ah0, ah1, ah2, ah3, bh[t2][2], bh[t2][3]);
        }
#pragma unroll
        for (int t2 = 0; t2 < 4; t2++) {
            mma_bf16(acc[2 * t2],     al0, al1, al2, al3, bh[t2][0], bh[t2][1]);
            mma_bf16(acc[2 * t2 + 1], al0, al1, al2, al3, bh[t2][2], bh[t2][3]);
        }
#pragma unroll
        for (int t2 = 0; t2 < 4; t2++) {
            mma_bf16(acc[2 * t2],     ah0, ah1, ah2, ah3, bl[t2][0], bl[t2][1]);
            mma_bf16(acc[2 * t2 + 1], ah0, ah1, ah2, ah3, bl[t2][2], bl[t2][3]);
        }
    }
}

// partial l (l = 0..2): g_oacc (+)= h_l @ Wout_l^T  (grid NT)
__global__ void __launch_bounds__(256, 1)
k_part(int l, int first) {
    extern __shared__ char sm[];
    int tid = threadIdx.x, wid = tid >> 5, lane = tid & 31;
    int quad = lane >> 2, qi = lane & 3;
    uint32_t sb = smem_u32(sm);
    int t = blockIdx.x;

    float acc[8][4];
    part_body(l, t, tid, wid, lane, sb, acc);

    int rA = t * 128 + wid * 16 + quad, rB = rA + 8;
#pragma unroll
    for (int q = 0; q < 8; q++) {
        int c = q * 8 + qi * 2;
        float2* pA = (float2*)&g_oacc[(size_t)rA * 64 + c];
        float2* pB = (float2*)&g_oacc[(size_t)rB * 64 + c];
        float2 vA = make_float2(acc[q][0], acc[q][1]);
        float2 vB = make_float2(acc[q][2], acc[q][3]);
        if (!first) {
            float2 oA = *pA, oB = *pB;
            vA.x += oA.x; vA.y += oA.y;
            vB.x += oB.x; vB.y += oB.y;
        }
        *pA = vA;
        *pB = vB;
    }
}

// tail: out = softmax(g_oacc + h_3 @ Wout_3^T + b)  (grid NT)
__global__ void __launch_bounds__(256, 1)
k_part_final(const float* __restrict__ bias, float* __restrict__ out, int nrows) {
    extern __shared__ char sm[];
    int tid = threadIdx.x, wid = tid >> 5, lane = tid & 31;
    int quad = lane >> 2, qi = lane & 3;
    uint32_t sb = smem_u32(sm);
    int t = blockIdx.x;

    float acc[8][4];
    part_body(3, t, tid, wid, lane, sb, acc);

    int rA = t * 128 + wid * 16 + quad, rB = rA + 8;
    float vA[16], vB[16];
#pragma unroll
    for (int q = 0; q < 8; q++) {
        int c = q * 8 + qi * 2;
        float2 oA = *(const float2*)&g_oacc[(size_t)rA * 64 + c];
        float2 oB = *(const float2*)&g_oacc[(size_t)rB * 64 + c];
        float bx = bias[c], by = bias[c + 1];
        vA[2 * q] = acc[q][0] + oA.x + bx; vA[2 * q + 1] = acc[q][1] + oA.y + by;
        vB[2 * q] = acc[q][2] + oB.x + bx; vB[2 * q + 1] = acc[q][3] + oB.y + by;
    }
    float mA = vA[0], mB = vB[0];
#pragma unroll
    for (int j = 1; j < 16; j++) { mA = fmaxf(mA, vA[j]); mB = fmaxf(mB, vB[j]); }
    mA = fmaxf(mA, __shfl_xor_sync(0xffffffffu, mA, 1));
    mA = fmaxf(mA, __shfl_xor_sync(0xffffffffu, mA, 2));
    mB = fmaxf(mB, __shfl_xor_sync(0xffffffffu, mB, 1));
    mB = fmaxf(mB, __shfl_xor_sync(0xffffffffu, mB, 2));
    float sA = 0.f, sB = 0.f;
#pragma unroll
    for (int j = 0; j < 16; j++) {
        vA[j] = __expf(vA[j] - mA); sA += vA[j];
        vB[j] = __expf(vB[j] - mB); sB += vB[j];
    }
    sA += __shfl_xor_sync(0xffffffffu, sA, 1);
    sA += __shfl_xor_sync(0xffffffffu, sA, 2);
    sB += __shfl_xor_sync(0xffffffffu, sB, 1);
    sB += __shfl_xor_sync(0xffffffffu, sB, 2);
    float iA = 1.0f / sA, iB = 1.0f / sB;
#pragma unroll
    for (int q = 0; q < 8; q++) {
        int c = q * 8 + qi * 2;
        if (rA < nrows)
            *(float2*)&out[(size_t)rA * 64 + c] = make_float2(vA[2 * q] * iA, vA[2 * q + 1] * iA);
        if (rB < nrows)
            *(float2*)&out[(size_t)rB * 64 + c] = make_float2(vB[2 * q] * iB, vB[2 * q + 1] * iB);
    }
}

// ---------------- host -------------------------------------------------------
extern "C" void kernel_launch(void* const* d_in, const int* in_sizes, int n_in,
                              void* d_out, int out_size) {
    const float* x       = (const float*)d_in[0];
    const void*  ei      = d_in[1];
    const float* W_in    = (const float*)d_in[2];
    const float* b_in    = (const float*)d_in[3];
    const float* W_convs = (const float*)d_in[4];
    const float* b_convs = (const float*)d_in[5];
    const float* W_out   = (const float*)d_in[6];
    const float* b_out   = (const float*)d_in[7];
    float* out = (float*)d_out;

    __nv_bfloat16 *hb, *tb, *wb;
    cudaGetSymbolAddress((void**)&hb, g_hb);
    cudaGetSymbolAddress((void**)&tb, g_tb);
    cudaGetSymbolAddress((void**)&wb, g_Wb);

    const int SMEM_G = 208896;
    const int SMEM_P = 104448;
    cudaFuncSetAttribute(k_gemm_p,     cudaFuncAttributeMaxDynamicSharedMemorySize, SMEM_G);
    cudaFuncSetAttribute(k_part,       cudaFuncAttributeMaxDynamicSharedMemorySize, SMEM_P);
    cudaFuncSetAttribute(k_part_final, cudaFuncAttributeMaxDynamicSharedMemorySize, SMEM_P);

    const int EB = (NE + 255) / 256;
    const int NB = (NN + 255) / 256;
    const int SB = (NN + 1023) / 1024;

    // ONE side stream only (a second stream pulls a fresh 2MB driver pool chunk
    // that outlives the graph and fails the teardown memory check — R15 evidence).
    // Stream/events created on the capture call; host code doesn't rerun on replay.
    cudaStream_t s1;
    cudaStreamCreateWithFlags(&s1, cudaStreamNonBlocking);
    cudaEvent_t eF, eJ, e0, e1, e2, eP;
    cudaEventCreateWithFlags(&eF, cudaEventDisableTiming);
    cudaEventCreateWithFlags(&eJ, cudaEventDisableTiming);
    cudaEventCreateWithFlags(&e0, cudaEventDisableTiming);
    cudaEventCreateWithFlags(&e1, cudaEventDisableTiming);
    cudaEventCreateWithFlags(&e2, cudaEventDisableTiming);
    cudaEventCreateWithFlags(&eP, cudaEventDisableTiming);

    cudaEventRecord(eF, 0);
    cudaStreamWaitEvent(s1, eF, 0);

    // side stream: CSR build + W_out prep, then partial finals (serialized here,
    // which also makes the g_oacc read-modify-write race-free)
    k_detect<<<1, 32, 0, s1>>>((const unsigned*)ei);
    k_zero<<<NB, 256, 0, s1>>>();
    k_decode<<<EB, 256, 0, s1>>>(ei);
    k_scan1<<<SB, 1024, 0, s1>>>();
    k_scan2<<<1, 128, 0, s1>>>(SB);
    k_scan3<<<SB, 1024, 0, s1>>>();
    k_fill<<<EB, 256, 0, s1>>>();
    k_prepWo<<<32, 256, 0, s1>>>(W_out);
    cudaEventRecord(eJ, s1);

    // main: input prep + input projection GEMM (h0)
    k_prepX<<<(NN * 32 + 255) / 256, 256>>>(x);
    k_prepW<<<64, 256>>>(W_in, W_convs);
    k_gemm_p<<<PGRID, 256, SMEM_G>>>(tb, wb, b_in, hb, NN);
    cudaEventRecord(e0, 0);

    // side stream: partial 0 (needs h0; prepWo already ordered on s1)
    cudaStreamWaitEvent(s1, e0, 0);
    k_part<<<NT, 256, SMEM_P, s1>>>(0, 1);

    // main joins CSR before first aggregation
    cudaStreamWaitEvent(0, eJ, 0);

    // layer 1
    k_agg<<<(NN * 32 + 255) / 256, 256>>>(hb);
    k_gemm_p<<<PGRID, 256, SMEM_G>>>(tb, wb + (size_t)1 * 2 * 16384,
                                     b_convs, hb + (size_t)1 * 2 * NR * HID, NN);
    cudaEventRecord(e1, 0);
    cudaStreamWaitEvent(s1, e1, 0);
    k_part<<<NT, 256, SMEM_P, s1>>>(1, 0);

    // layer 2
    k_agg<<<(NN * 32 + 255) / 256, 256>>>(hb + (size_t)1 * 2 * NR * HID);
    k_gemm_p<<<PGRID, 256, SMEM_G>>>(tb, wb + (size_t)2 * 2 * 16384,
                                     b_convs + 128, hb + (size_t)2 * 2 * NR * HID, NN);
    cudaEventRecord(e2, 0);
    cudaStreamWaitEvent(s1, e2, 0);
    k_part<<<NT, 256, SMEM_P, s1>>>(2, 0);
    cudaEventRecord(eP, s1);

    // layer 3
    k_agg<<<(NN * 32 + 255) / 256, 256>>>(hb + (size_t)2 * 2 * NR * HID);
    k_gemm_p<<<PGRID, 256, SMEM_G>>>(tb, wb + (size_t)3 * 2 * 16384,
                                     b_convs + 256, hb + (size_t)3 * 2 * NR * HID, NN);

    // tail: partial 3 + bias + softmax (needs h3 + completed g_oacc)
    cudaStreamWaitEvent(0, eP, 0);
    k_part_final<<<NT, 256, SMEM_P>>>(b_out, out, NN);
}

// round 17
// speedup vs baseline: 1.1171x; 1.1171x over previous
#include <cuda_runtime.h>
#include <cuda_bf16.h>
#include <cstdint>

#define NN 100000
#define NR 100096   // rows padded to 128-multiple: guard-free tile staging
#define NT 782      // NR / 128 (final kernel tiles)
#define NT2 1564    // NR / 64  (gemm tiles)
#define NE 600000
#define HID 128
#define OUTD 64
#define PGRID 148   // persistent grid

// ---------------- scratch (device globals; no allocations allowed) ----------
__device__ __nv_bfloat16 g_hb[4 * 2 * NR * HID];  // h states: hi/lo planes
__device__ __nv_bfloat16 g_tb[2 * NR * HID];      // t images (also x images)
__device__ __nv_bfloat16 g_Wb[4 * 2 * HID * HID]; // per layer: hi[128][128], lo
__device__ __nv_bfloat16 g_WoB[2 * OUTD * 512];   // W_out: hi[64][512], lo
__device__ int   g_off[NN + 1];
__device__ int   g_deg[NN];
__device__ int   g_cur[NN];
__device__ int   g_srcs[NE];
__device__ int   g_src[NE];
__device__ int   g_dst[NE];
__device__ int   g_is64;
__device__ int   g_bsum[128];

// ---------------- helpers -----------------------------------------------------
__device__ __forceinline__ uint32_t smem_u32(const void* p) {
    uint32_t a;
    asm("{ .reg .u64 t; cvta.to.shared.u64 t, %1; cvt.u32.u64 %0, t; }" : "=r"(a) : "l"(p));
    return a;
}
__device__ __forceinline__ float lo16f(uint32_t u) { return __uint_as_float(u << 16); }
__device__ __forceinline__ float hi16f(uint32_t u) { return __uint_as_float(u & 0xffff0000u); }

__device__ __forceinline__ void split2(float a, float b, uint32_t& hw, uint32_t& lw) {
    __nv_bfloat16 ha = __float2bfloat16_rn(a), hb = __float2bfloat16_rn(b);
    __nv_bfloat16 la = __float2bfloat16_rn(a - __bfloat162float(ha));
    __nv_bfloat16 lb = __float2bfloat16_rn(b - __bfloat162float(hb));
    hw = (uint32_t)__bfloat16_as_ushort(ha) | ((uint32_t)__bfloat16_as_ushort(hb) << 16);
    lw = (uint32_t)__bfloat16_as_ushort(la) | ((uint32_t)__bfloat16_as_ushort(lb) << 16);
}
__device__ __forceinline__ void split4(float4 v, uint2& hi, uint2& lo) {
    split2(v.x, v.y, hi.x, lo.x);
    split2(v.z, v.w, hi.y, lo.y);
}

__device__ __forceinline__ void mma_bf16(float* c, uint32_t a0, uint32_t a1,
                                         uint32_t a2, uint32_t a3,
                                         uint32_t b0, uint32_t b1) {
    asm volatile(
        "mma.sync.aligned.m16n8k16.row.col.f32.bf16.bf16.f32 "
        "{%0,%1,%2,%3},{%4,%5,%6,%7},{%8,%9},{%0,%1,%2,%3};"
        : "+f"(c[0]), "+f"(c[1]), "+f"(c[2]), "+f"(c[3])
        : "r"(a0), "r"(a1), "r"(a2), "r"(a3), "r"(b0), "r"(b1));
}

#define LDM4(r0, r1, r2, r3, addr) \
    asm volatile("ldmatrix.sync.aligned.m8n8.x4.shared.b16 {%0,%1,%2,%3}, [%4];" \
                 : "=r"(r0), "=r"(r1), "=r"(r2), "=r"(r3) : "r"(addr))

#define CPA16(dst, src) \
    asm volatile("cp.async.cg.shared.global [%0], [%1], 16;" :: "r"(dst), "l"(src) : "memory")
#define CPA_COMMIT() asm volatile("cp.async.commit_group;" ::: "memory")
#define CPA_WAIT0()  asm volatile("cp.async.wait_group 0;" ::: "memory")
#define CPA_WAIT1()  asm volatile("cp.async.wait_group 1;" ::: "memory")

// ---------------- edge dtype detection + decode + degree count ---------------
__global__ void k_detect(const unsigned* __restrict__ raw) {
    if (threadIdx.x == 0) {
        int is64 = 1;
        for (int i = 1; i < 128; i += 2)
            if (raw[i] != 0u) { is64 = 0; break; }
        g_is64 = is64;
    }
}

__global__ void k_zero() {
    int i = blockIdx.x * blockDim.x + threadIdx.x;
    if (i < NN) { g_deg[i] = 0; g_cur[i] = 0; }
}

__global__ void k_decode(const void* __restrict__ raw) {
    int e = blockIdx.x * blockDim.x + threadIdx.x;
    if (e >= NE) return;
    int s, d;
    if (g_is64) {
        const long long* p = (const long long*)raw;
        s = (int)p[e]; d = (int)p[NE + e];
    } else {
        const int* p = (const int*)raw;
        s = p[e]; d = p[NE + e];
    }
    g_src[e] = s;
    g_dst[e] = d;
    atomicAdd(&g_deg[d], 1);
}

// ---------------- CSR build ---------------------------------------------------
__global__ void k_scan1() {
    __shared__ int sh[1024];
    int i = blockIdx.x * 1024 + threadIdx.x;
    int v = (i < NN) ? g_deg[i] : 0;
    sh[threadIdx.x] = v;
    __syncthreads();
    for (int s = 1; s < 1024; s <<= 1) {
        int a = (threadIdx.x >= (unsigned)s) ? sh[threadIdx.x - s] : 0;
        __syncthreads();
        sh[threadIdx.x] += a;
        __syncthreads();
    }
    if (i < NN) g_deg[i] = sh[threadIdx.x];
    if (threadIdx.x == 1023) g_bsum[blockIdx.x] = sh[1023];
}
__global__ void k_scan2(int nb) {
    __shared__ int sh[128];
    int t = threadIdx.x;
    sh[t] = (t < nb) ? g_bsum[t] : 0;
    __syncthreads();
    if (t == 0) {
        int acc = 0;
        for (int i = 0; i < nb; i++) { int v = sh[i]; sh[i] = acc; acc += v; }
    }
    __syncthreads();
    if (t < nb) g_bsum[t] = sh[t];
}
__global__ void k_scan3() {
    int i = blockIdx.x * 1024 + threadIdx.x;
    if (i < NN) g_off[i + 1] = g_deg[i] + g_bsum[blockIdx.x];
    if (i == 0) g_off[0] = 0;
}
__global__ void k_fill() {
    int e = blockIdx.x * blockDim.x + threadIdx.x;
    if (e >= NE) return;
    int d = g_dst[e];
    int p = atomicAdd(&g_cur[d], 1);
    g_srcs[g_off[d] + p] = g_src[e];
}

// ---------------- weight / input preconversion (bf16 hi/lo images) ----------
__global__ void k_prepW(const float* __restrict__ W_in, const float* __restrict__ W_convs) {
    int idx = blockIdx.x * blockDim.x + threadIdx.x;   // 4*128*32
    if (idx >= 4 * 128 * 32) return;
    int l = idx >> 12;
    int rem = idx & 4095;
    int j = rem >> 5;
    int k4 = rem & 31;
    const float* W = (l == 0) ? W_in : (W_convs + (size_t)(l - 1) * 128 * 128);
    float4 v = ((const float4*)W)[j * 32 + k4];
    uint2 hp, lp; split4(v, hp, lp);
    char* base = (char*)(g_Wb + (size_t)l * 2 * 16384);
    *(uint2*)(base + j * 256 + k4 * 8) = hp;
    *(uint2*)(base + 32768 + j * 256 + k4 * 8) = lp;
}

__global__ void k_prepWo(const float* __restrict__ W_out) {
    int idx = blockIdx.x * blockDim.x + threadIdx.x;   // 64*128
    if (idx >= 64 * 128) return;
    int j = idx >> 7;
    int k4 = idx & 127;
    float4 v = ((const float4*)W_out)[j * 128 + k4];
    uint2 hp, lp; split4(v, hp, lp);
    char* base = (char*)g_WoB;
    *(uint2*)(base + j * 1024 + k4 * 8) = hp;
    *(uint2*)(base + 65536 + j * 1024 + k4 * 8) = lp;
}

__global__ void k_prepX(const float* __restrict__ x) {
    int i = blockIdx.x * blockDim.x + threadIdx.x;
    if (i >= NN * 32) return;
    float4 v = ((const float4*)x)[i];
    uint2 hp, lp; split4(v, hp, lp);
    ((uint2*)g_tb)[i] = hp;
    ((uint2*)(g_tb + (size_t)NR * HID))[i] = lp;
}

// ---------------- aggregation on images: t = h + seg_sum(h) ------------------
__global__ void k_agg(const __nv_bfloat16* __restrict__ himg) {
    int gw   = (blockIdx.x * blockDim.x + threadIdx.x) >> 5;
    int lane = threadIdx.x & 31;
    if (gw >= NN) return;
    const uint2* Hv = (const uint2*)himg;
    const uint2* Lv = (const uint2*)(himg + (size_t)NR * HID);
    size_t idx = (size_t)gw * 32 + lane;
    uint2 h = Hv[idx], l = Lv[idx];
    float a0 = lo16f(h.x) + lo16f(l.x);
    float a1 = hi16f(h.x) + hi16f(l.x);
    float a2 = lo16f(h.y) + lo16f(l.y);
    float a3 = hi16f(h.y) + hi16f(l.y);
    int s0 = g_off[gw], s1 = g_off[gw + 1];
    for (int j = s0; j < s1; j++) {
        size_t si = (size_t)g_srcs[j] * 32 + lane;
        uint2 hh = Hv[si], ll = Lv[si];
        a0 += lo16f(hh.x) + lo16f(ll.x);
        a1 += hi16f(hh.x) + hi16f(ll.x);
        a2 += lo16f(hh.y) + lo16f(ll.y);
        a3 += hi16f(hh.y) + hi16f(ll.y);
    }
    uint2 hp, lp;
    split2(a0, a1, hp.x, lp.x);
    split2(a2, a3, hp.y, lp.y);
    ((uint2*)g_tb)[idx] = hp;
    ((uint2*)(g_tb + (size_t)NR * HID))[idx] = lp;
}

// ---------------- persistent HMMA GEMM: C = A @ W^T + b ----------------------
// grid 148, 1 CTA/SM. Resident full-K W hi/lo (69632B) staged once; 64-row A
// tiles double-buffered (34816B each; NT2=1564 -> per-CTA 10.57, ceil 11 = 4%
// imbalance vs 13.6% at 128-row tiles). Warps 2(M)x4(N), warp tile 32x32.
#define SP 272
#define ABUF 69632
__global__ void __launch_bounds__(256, 1)
k_gemm_p(const __nv_bfloat16* __restrict__ Aimg, const __nv_bfloat16* __restrict__ Wimg,
         const float* __restrict__ bias, __nv_bfloat16* __restrict__ Cimg, int nrows) {
    extern __shared__ char sm[];
    int tid = threadIdx.x, wid = tid >> 5, lane = tid & 31;
    int quad = lane >> 2, qi = lane & 3;
    int wm = wid >> 2, wn = wid & 3;
    uint32_t sb = smem_u32(sm);

    // stage W (hi+lo, 4096 x 16B) — once per CTA
    for (int i = tid; i < 4096; i += 256) {
        int pl = i >> 11, j = i & 2047, r = j >> 4, seg = (j & 15) * 16;
        CPA16(sb + pl * 34816 + r * SP + seg,
              (const char*)Wimg + pl * 32768 + r * 256 + seg);
    }
    // stage 64-row A tile t into buffer b
    auto stageA = [&](int t, int b) {
        uint32_t base = sb + ABUF + b * 34816;
        const char* A0 = (const char*)Aimg;
        for (int i = tid; i < 2048; i += 256) {
            int pl = i >> 10, j = i & 1023, r = j >> 4, seg = (j & 15) * 16;
            CPA16(base + pl * 17408 + r * SP + seg,
                  A0 + (size_t)pl * NR * 256 + (size_t)(t * 64 + r) * 256 + seg);
        }
    };

    int t0 = blockIdx.x;
    stageA(t0, 0);
    CPA_COMMIT();          // group: W + A(t0)

    uint32_t brow = (uint32_t)(((((lane >> 4) << 3) + (lane & 7)) * SP) + ((lane >> 3) & 1) * 16);
    uint32_t bH = sb + brow + (uint32_t)(wn * 32 * SP);
    uint32_t bL = bH + 34816;

    int b = 0;
    for (int t = t0; t < NT2; t += PGRID, b ^= 1) {
        int tn = t + PGRID;
        if (tn < NT2) { stageA(tn, b ^ 1); CPA_COMMIT(); CPA_WAIT1(); }
        else CPA_WAIT0();
        __syncthreads();

        float acc[2][4][4];
#pragma unroll
        for (int mi = 0; mi < 2; mi++)
#pragma unroll
            for (int nj = 0; nj < 4; nj++)
#pragma unroll
                for (int c = 0; c < 4; c++) acc[mi][nj][c] = 0.f;

        uint32_t abase = sb + ABUF + b * 34816;
        uint32_t aH = abase + (uint32_t)((wm * 32 + (lane & 15)) * SP + (lane >> 4) * 16);
        uint32_t aL = aH + 17408;

        for (int s = 0; s < 8; s++) {
            uint32_t ah[2][4], al[2][4], bh[8], bl[8];
#pragma unroll
            for (int mi = 0; mi < 2; mi++) {
                LDM4(ah[mi][0], ah[mi][1], ah[mi][2], ah[mi][3], aH + mi * (16 * SP) + s * 32);
                LDM4(al[mi][0], al[mi][1], al[mi][2], al[mi][3], aL + mi * (16 * SP) + s * 32);
            }
#pragma unroll
            for (int nj = 0; nj < 2; nj++) {
                LDM4(bh[4 * nj], bh[4 * nj + 1], bh[4 * nj + 2], bh[4 * nj + 3],
                     bH + nj * (16 * SP) + s * 32);
                LDM4(bl[4 * nj], bl[4 * nj + 1], bl[4 * nj + 2], bl[4 * nj + 3],
                     bL + nj * (16 * SP) + s * 32);
            }
#pragma unroll
            for (int mi = 0; mi < 2; mi++)
#pragma unroll
                for (int nj = 0; nj < 2; nj++) {
                    mma_bf16(acc[mi][2 * nj],     ah[mi][0], ah[mi][1], ah[mi][2], ah[mi][3],
                             bh[4 * nj], bh[4 * nj + 1]);
                    mma_bf16(acc[mi][2 * nj + 1], ah[mi][0], ah[mi][1], ah[mi][2], ah[mi][3],
                             bh[4 * nj + 2], bh[4 * nj + 3]);
                }
#pragma unroll
            for (int mi = 0; mi < 2; mi++)
#pragma unroll
                for (int nj = 0; nj < 2; nj++) {
                    mma_bf16(acc[mi][2 * nj],     al[mi][0], al[mi][1], al[mi][2], al[mi][3],
                             bh[4 * nj], bh[4 * nj + 1]);
                    mma_bf16(acc[mi][2 * nj + 1], al[mi][0], al[mi][1], al[mi][2], al[mi][3],
                             bh[4 * nj + 2], bh[4 * nj + 3]);
                }
#pragma unroll
            for (int mi = 0; mi < 2; mi++)
#pragma unroll
                for (int nj = 0; nj < 2; nj++) {
                    mma_bf16(acc[mi][2 * nj],     ah[mi][0], ah[mi][1], ah[mi][2], ah[mi][3],
                             bl[4 * nj], bl[4 * nj + 1]);
                    mma_bf16(acc[mi][2 * nj + 1], ah[mi][0], ah[mi][1], ah[mi][2], ah[mi][3],
                             bl[4 * nj + 2], bl[4 * nj + 3]);
                }
        }

        // epilogue: bias, split, store image planes
        char* Ch = (char*)Cimg;
        char* Cl = Ch + (size_t)NR * 256;
        int row0 = t * 64;
#pragma unroll
        for (int mi = 0; mi < 2; mi++) {
            int rA = row0 + wm * 32 + mi * 16 + quad, rB = rA + 8;
#pragma unroll
            for (int nj = 0; nj < 4; nj++) {
                int c = wn * 32 + nj * 8 + qi * 2;
                float bx = bias[c], by = bias[c + 1];
                uint32_t hw, lw;
                if (rA < nrows) {
                    split2(acc[mi][nj][0] + bx, acc[mi][nj][1] + by, hw, lw);
                    *(uint32_t*)(Ch + (size_t)rA * 256 + c * 2) = hw;
                    *(uint32_t*)(Cl + (size_t)rA * 256 + c * 2) = lw;
                }
                if (rB < nrows) {
                    split2(acc[mi][nj][2] + bx, acc[mi][nj][3] + by, hw, lw);
                    *(uint32_t*)(Ch + (size_t)rB * 256 + c * 2) = hw;
                    *(uint32_t*)(Cl + (size_t)rB * 256 + c * 2) = lw;
                }
            }
        }
        __syncthreads();
    }
}

// ---------------- persistent final: softmax(cat(h) @ Wout^T + b) -------------
#define SFW 1040
#define SFA 144
#define FABUF 133120
__global__ void __launch_bounds__(256, 1)
k_final_p(const float* __restrict__ bias, float* __restrict__ out, int nrows) {
    extern __shared__ char sm[];
    int tid = threadIdx.x, wid = tid >> 5, lane = tid & 31;
    int quad = lane >> 2, qi = lane & 3;
    uint32_t sb = smem_u32(sm);

    for (int i = tid; i < 8192; i += 256) {
        int pl = i >> 12, j = i & 4095, r = j >> 6, seg = (j & 63) * 16;
        CPA16(sb + pl * 66560 + r * SFW + seg,
              (const char*)g_WoB + pl * 65536 + (size_t)r * 1024 + seg);
    }
    auto stageA = [&](int t, int kc, int b) {
        uint32_t base = sb + FABUF + b * 36864;
        int st = kc >> 1, half = (kc & 1) * 128;
        for (int i = tid; i < 2048; i += 256) {
            int pl = i >> 10, j = i & 1023, r = j >> 3, seg = (j & 7) * 16;
            CPA16(base + pl * 18432 + r * SFA + seg,
                  (const char*)g_hb + (size_t)(st * 2 + pl) * NR * 256
                  + (size_t)(t * 128 + r) * 256 + half + seg);
        }
    };

    int t0 = blockIdx.x;
    stageA(t0, 0, 0);
    CPA_COMMIT();

    uint32_t brow = (uint32_t)(((((lane >> 4) << 3) + (lane & 7)) * SFW) + ((lane >> 3) & 1) * 16);
    uint32_t aHr = (uint32_t)((wid * 16 + (lane & 15)) * SFA + (lane >> 4) * 16);

    int b = 0;
    for (int t = t0; t < NT; t += PGRID) {
        float acc[8][4];
#pragma unroll
        for (int q = 0; q < 8; q++)
#pragma unroll
            for (int c = 0; c < 4; c++) acc[q][c] = 0.f;

        for (int kc = 0; kc < 8; kc++, b ^= 1) {
            int nt = (kc < 7) ? t : t + PGRID;
            int nkc = (kc < 7) ? kc + 1 : 0;
            if (nt < NT) { stageA(nt, nkc, b ^ 1); CPA_COMMIT(); CPA_WAIT1(); }
            else CPA_WAIT0();
            __syncthreads();

            uint32_t aH = sb + FABUF + b * 36864 + aHr;
            uint32_t aL = aH + 18432;
            uint32_t bHb = sb + brow + (uint32_t)(kc * 128);
            uint32_t bLb = bHb + 66560;

            for (int s = 0; s < 4; s++) {
                uint32_t ah0, ah1, ah2, ah3, al0, al1, al2, al3;
                uint32_t bh[4][4], bl[4][4];
                LDM4(ah0, ah1, ah2, ah3, aH + s * 32);
                LDM4(al0, al1, al2, al3, aL + s * 32);
#pragma unroll
                for (int t2 = 0; t2 < 4; t2++) {
                    LDM4(bh[t2][0], bh[t2][1], bh[t2][2], bh[t2][3], bHb + t2 * (16 * SFW) + s * 32);
                    LDM4(bl[t2][0], bl[t2][1], bl[t2][2], bl[t2][3], bLb + t2 * (16 * SFW) + s * 32);
                }
#pragma unroll
                for (int t2 = 0; t2 < 4; t2++) {
                    mma_bf16(acc[2 * t2],     ah0, ah1, ah2, ah3, bh[t2][0], bh[t2][1]);
                    mma_bf16(acc[2 * t2 + 1], ah0, ah1, ah2, ah3, bh[t2][2], bh[t2][3]);
                }
#pragma unroll
                for (int t2 = 0; t2 < 4; t2++) {
                    mma_bf16(acc[2 * t2],     al0, al1, al2, al3, bh[t2][0], bh[t2][1]);
                    mma_bf16(acc[2 * t2 + 1], al0, al1, al2, al3, bh[t2][2], bh[t2][3]);
                }
#pragma unroll
                for (int t2 = 0; t2 < 4; t2++) {
                    mma_bf16(acc[2 * t2],     ah0, ah1, ah2, ah3, bl[t2][0], bl[t2][1]);
                    mma_bf16(acc[2 * t2 + 1], ah0, ah1, ah2, ah3, bl[t2][2], bl[t2][3]);
                }
            }
            __syncthreads();
        }

        int rA = t * 128 + wid * 16 + quad, rB = rA + 8;
        float vA[16], vB[16];
#pragma unroll
        for (int q = 0; q < 8; q++) {
            int c = q * 8 + qi * 2;
            float bx = bias[c], by = bias[c + 1];
            vA[2 * q] = acc[q][0] + bx; vA[2 * q + 1] = acc[q][1] + by;
            vB[2 * q] = acc[q][2] + bx; vB[2 * q + 1] = acc[q][3] + by;
        }
        float mA = vA[0], mB = vB[0];
#pragma unroll
        for (int j = 1; j < 16; j++) { mA = fmaxf(mA, vA[j]); mB = fmaxf(mB, vB[j]); }
        mA = fmaxf(mA, __shfl_xor_sync(0xffffffffu, mA, 1));
        mA = fmaxf(mA, __shfl_xor_sync(0xffffffffu, mA, 2));
        mB = fmaxf(mB, __shfl_xor_sync(0xffffffffu, mB, 1));
        mB = fmaxf(mB, __shfl_xor_sync(0xffffffffu, mB, 2));
        float sA = 0.f, sB = 0.f;
#pragma unroll
        for (int j = 0; j < 16; j++) {
            vA[j] = __expf(vA[j] - mA); sA += vA[j];
            vB[j] = __expf(vB[j] - mB); sB += vB[j];
        }
        sA += __shfl_xor_sync(0xffffffffu, sA, 1);
        sA += __shfl_xor_sync(0xffffffffu, sA, 2);
        sB += __shfl_xor_sync(0xffffffffu, sB, 1);
        sB += __shfl_xor_sync(0xffffffffu, sB, 2);
        float iA = 1.0f / sA, iB = 1.0f / sB;
#pragma unroll
        for (int q = 0; q < 8; q++) {
            int c = q * 8 + qi * 2;
            if (rA < nrows)
                *(float2*)&out[(size_t)rA * 64 + c] = make_float2(vA[2 * q] * iA, vA[2 * q + 1] * iA);
            if (rB < nrows)
                *(float2*)&out[(size_t)rB * 64 + c] = make_float2(vB[2 * q] * iB, vB[2 * q + 1] * iB);
        }
    }
}

// ---------------- host -------------------------------------------------------
extern "C" void kernel_launch(void* const* d_in, const int* in_sizes, int n_in,
                              void* d_out, int out_size) {
    const float* x       = (const float*)d_in[0];
    const void*  ei      = d_in[1];
    const float* W_in    = (const float*)d_in[2];
    const float* b_in    = (const float*)d_in[3];
    const float* W_convs = (const float*)d_in[4];
    const float* b_convs = (const float*)d_in[5];
    const float* W_out   = (const float*)d_in[6];
    const float* b_out   = (const float*)d_in[7];
    float* out = (float*)d_out;

    __nv_bfloat16 *hb, *tb, *wb;
    cudaGetSymbolAddress((void**)&hb, g_hb);
    cudaGetSymbolAddress((void**)&tb, g_tb);
    cudaGetSymbolAddress((void**)&wb, g_Wb);

    const int SMEM_G = 139264;   // 69632 W + 2x34816 A buffers
    const int SMEM_F = 206848;   // 133120 W_out + 2x36864 A buffers
    cudaFuncSetAttribute(k_gemm_p,  cudaFuncAttributeMaxDynamicSharedMemorySize, SMEM_G);
    cudaFuncSetAttribute(k_final_p, cudaFuncAttributeMaxDynamicSharedMemorySize, SMEM_F);

    const int EB = (NE + 255) / 256;
    const int NB = (NN + 255) / 256;
    const int SB = (NN + 1023) / 1024;

    // ONE side stream (R15: a second stream leaks a 2MB driver pool chunk).
    cudaStream_t s1;
    cudaStreamCreateWithFlags(&s1, cudaStreamNonBlocking);
    cudaEvent_t eF, eJ;
    cudaEventCreateWithFlags(&eF, cudaEventDisableTiming);
    cudaEventCreateWithFlags(&eJ, cudaEventDisableTiming);

    cudaEventRecord(eF, 0);
    cudaStreamWaitEvent(s1, eF, 0);

    // side stream: CSR build + W_out prep (overlaps input GEMM)
    k_detect<<<1, 32, 0, s1>>>((const unsigned*)ei);
    k_zero<<<NB, 256, 0, s1>>>();
    k_decode<<<EB, 256, 0, s1>>>(ei);
    k_scan1<<<SB, 1024, 0, s1>>>();
    k_scan2<<<1, 128, 0, s1>>>(SB);
    k_scan3<<<SB, 1024, 0, s1>>>();
    k_fill<<<EB, 256, 0, s1>>>();
    k_prepWo<<<32, 256, 0, s1>>>(W_out);
    cudaEventRecord(eJ, s1);

    // main: input prep + input projection GEMM
    k_prepX<<<(NN * 32 + 255) / 256, 256>>>(x);
    k_prepW<<<64, 256>>>(W_in, W_convs);
    k_gemm_p<<<PGRID, 256, SMEM_G>>>(tb, wb, b_in, hb, NN);

    // join CSR before first aggregation
    cudaStreamWaitEvent(0, eJ, 0);

    // 3 GIN layers: gather on images, then persistent GEMM
    for (int l = 0; l < 3; l++) {
        k_agg<<<(NN * 32 + 255) / 256, 256>>>(hb + (size_t)l * 2 * NR * HID);
        k_gemm_p<<<PGRID, 256, SMEM_G>>>(tb, wb + (size_t)(1 + l) * 2 * 16384,
                                         b_convs + (size_t)l * HID,
                                         hb + (size_t)(l + 1) * 2 * NR * HID, NN);
    }

    // output projection + fused softmax
    k_final_p<<<PGRID, 256, SMEM_F>>>(b_out, out, NN);
}